// round 13
// baseline (speedup 1.0000x reference)
#include <cuda_runtime.h>
#include <cuda_fp16.h>
#include <math.h>
#include <stdint.h>

// Problem constants (fixed shapes)
#define Bb 2
#define Ll 2048
#define Dd 1024
#define Hh 16
#define Ee 64
#define TD 3072          // 3*D
#define Mrows 4096       // B*L
#define Kdim 1024
#define CL 128           // chunk length
#define NC 16            // chunks per (b,h) sequence

// ---------------------------------------------------------------------------
// Device scratch (no allocation allowed)
// ---------------------------------------------------------------------------
__device__ float g_qkv[(size_t)Mrows * TD];    // feature-mapped q,k and raw v (fp32)
__device__ float g_kv[(size_t)Bb * Hh * NC * Ee * Ee];  // per-chunk KV sums -> exclusive prefixes
__device__ float g_zc[(size_t)Bb * Hh * NC * Ee];       // per-chunk k sums  -> exclusive prefixes

// fp16 hi/lo splits
__device__ __half g_xh[(size_t)Mrows * Kdim];
__device__ __half g_xl[(size_t)Mrows * Kdim];
__device__ __half g_wqh[(size_t)TD * Kdim];
__device__ __half g_wql[(size_t)TD * Kdim];
__device__ __half g_woh[(size_t)Dd * Kdim];
__device__ __half g_wol[(size_t)Dd * Kdim];
__device__ __half g_ah[(size_t)Mrows * Kdim];   // attention output hi (written by chunk_attn)
__device__ __half g_al[(size_t)Mrows * Kdim];   // attention output lo

// ---------------------------------------------------------------------------
// PTX helpers (base sm_100 feature set: mma.sync, ldmatrix, cp.async)
// ---------------------------------------------------------------------------
__device__ __forceinline__ uint32_t smem_u32(const void* p) {
    uint32_t a;
    asm("{ .reg .u64 t; cvta.to.shared.u64 t, %1; cvt.u32.u64 %0, t; }" : "=r"(a) : "l"(p));
    return a;
}

#define CP16(dst, src) \
    asm volatile("cp.async.cg.shared.global [%0], [%1], 16;" :: "r"(dst), "l"(src))
#define CP_COMMIT() asm volatile("cp.async.commit_group;" ::: "memory")
#define CP_WAIT0()  asm volatile("cp.async.wait_group 0;" ::: "memory")

#define LDSM4(r0, r1, r2, r3, addr) \
    asm volatile("ldmatrix.sync.aligned.m8n8.x4.shared.b16 {%0,%1,%2,%3}, [%4];" \
        : "=r"(r0), "=r"(r1), "=r"(r2), "=r"(r3) : "r"(addr))

// fp16 operands, fp32 accumulator (main term)
#define MMAF(d, a, b) \
    asm volatile("mma.sync.aligned.m16n8k16.row.col.f32.f16.f16.f32 " \
        "{%0,%1,%2,%3},{%4,%5,%6,%7},{%8,%9},{%0,%1,%2,%3};" \
        : "+f"((d)[0]), "+f"((d)[1]), "+f"((d)[2]), "+f"((d)[3]) \
        : "r"((a)[0]), "r"((a)[1]), "r"((a)[2]), "r"((a)[3]), \
          "r"((b)[0]), "r"((b)[1]))

// fp16 operands, fp16 accumulator (correction terms; full-rate path)
#define MMAC(c, a, b) \
    asm volatile("mma.sync.aligned.m16n8k16.row.col.f16.f16.f16.f16 " \
        "{%0,%1},{%2,%3,%4,%5},{%6,%7},{%0,%1};" \
        : "+r"((c)[0]), "+r"((c)[1]) \
        : "r"((a)[0]), "r"((a)[1]), "r"((a)[2]), "r"((a)[3]), \
          "r"((b)[0]), "r"((b)[1]))

// ---------------------------------------------------------------------------
// fp16 split: hi = fp16(x), lo = fp16(x - hi)
// ---------------------------------------------------------------------------
__global__ __launch_bounds__(256)
void split_f16(const float* __restrict__ s, __half* __restrict__ h,
               __half* __restrict__ l, int n4) {
    int i = blockIdx.x * 256 + threadIdx.x;
    if (i >= n4) return;
    float4 v = ((const float4*)s)[i];
    __half h0 = __float2half_rn(v.x);
    __half h1 = __float2half_rn(v.y);
    __half h2 = __float2half_rn(v.z);
    __half h3 = __float2half_rn(v.w);
    __half l0 = __float2half_rn(v.x - __half2float(h0));
    __half l1 = __float2half_rn(v.y - __half2float(h1));
    __half l2 = __float2half_rn(v.z - __half2float(h2));
    __half l3 = __float2half_rn(v.w - __half2float(h3));
    ((__half2*)h)[2 * i]     = __half2(h0, h1);
    ((__half2*)h)[2 * i + 1] = __half2(h2, h3);
    ((__half2*)l)[2 * i]     = __half2(l0, l1);
    ((__half2*)l)[2 * i + 1] = __half2(l2, l3);
}

// ---------------------------------------------------------------------------
// mma.sync GEMM: C[M,N] = (Ah+Al)[M,K] @ (Bh+Bl)[N,K]^T + bias.
// fp16 3-term split: Ah*Bh in fp32-acc MMA; Ah*Bl + Al*Bh in fp16-acc MMA.
// 512 threads (16 warps as 4m x 4n, warp tile 32x32), 128x128x32 block tile,
// single-barrier double-buffered cp.async pipeline.
// ---------------------------------------------------------------------------
#define TPITCH 80
#define TSZ   (128 * TPITCH)
#define GSM   (2 * 4 * TSZ)

template<bool QKV>
__global__ __launch_bounds__(512)
void mma_gemm(const float* __restrict__ bias, float* __restrict__ Cp)
{
    constexpr int NTOT = QKV ? TD : Dd;
    extern __shared__ char sm[];
    const uint32_t sb = smem_u32(sm);

    const __half* Ahp = QKV ? g_xh : g_ah;
    const __half* Alp = QKV ? g_xl : g_al;
    const __half* Bhp = QKV ? g_wqh : g_woh;
    const __half* Blp = QKV ? g_wql : g_wol;
    float* C = QKV ? g_qkv : Cp;

    const int tid  = threadIdx.x;
    const int lane = tid & 31;
    const int wid  = tid >> 5;
    const int wm   = wid & 3;         // 0..3 (m, 32 rows each)
    const int wn   = wid >> 2;        // 0..3 (n, 32 cols each)
    const int m0   = blockIdx.y * 128;
    const int n0   = blockIdx.x * 128;

    // loader coords: 512 threads, one 16B chunk per thread per tile
    const int lrow = tid >> 2;            // 0..127
    const int lcb  = (tid & 3) * 16;      // byte col in smem row
    const int lce  = (tid & 3) * 8;       // element col in gmem row

    const __half* gsrc[4] = {
        Ahp + (size_t)m0 * Kdim, Alp + (size_t)m0 * Kdim,
        Bhp + (size_t)n0 * Kdim, Blp + (size_t)n0 * Kdim };

    float acc[2][4][4];                  // fp32 main accumulators
    uint32_t cacc[2][4][2];              // fp16 correction accumulators
    #pragma unroll
    for (int i = 0; i < 2; i++)
        #pragma unroll
        for (int j = 0; j < 4; j++) {
            #pragma unroll
            for (int r = 0; r < 4; r++) acc[i][j][r] = 0.f;
            cacc[i][j][0] = 0u; cacc[i][j][1] = 0u;
        }

    #define ISSUE(buf, kc) do {                                               \
        const int k0_ = (kc) * 32;                                            \
        const uint32_t db_ = sb + (buf) * 4 * TSZ;                            \
        _Pragma("unroll")                                                     \
        for (int t_ = 0; t_ < 4; t_++) {                                      \
            CP16(db_ + t_ * TSZ + lrow * TPITCH + lcb,                        \
                 gsrc[t_] + (size_t)lrow * Kdim + k0_ + lce);                 \
        }                                                                     \
    } while (0)

    ISSUE(0, 0); CP_COMMIT();

    const int r16 = lane & 15;
    const int kb8 = (lane >> 4) * 16;

    int buf = 0;
    for (int kc = 0; kc < Kdim / 32; kc++) {
        CP_WAIT0();                // chunk kc landed (only group in flight)
        __syncthreads();           // publish kc; all warps done with kc-1
        if (kc + 1 < Kdim / 32) { ISSUE(buf ^ 1, kc + 1); CP_COMMIT(); }

        const uint32_t base = sb + buf * 4 * TSZ;
        const uint32_t sAh = base, sAl = base + TSZ;
        const uint32_t sBh = base + 2 * TSZ, sBl = base + 3 * TSZ;

        #pragma unroll
        for (int ks = 0; ks < 2; ks++) {
            const int kbyte = ks * 32 + kb8;
            uint32_t ah[2][4], al[2][4], bh[4][2], bl[4][2];
            #pragma unroll
            for (int tm = 0; tm < 2; tm++) {
                const uint32_t roff = (uint32_t)(wm * 32 + tm * 16 + r16) * TPITCH + kbyte;
                LDSM4(ah[tm][0], ah[tm][1], ah[tm][2], ah[tm][3], sAh + roff);
                LDSM4(al[tm][0], al[tm][1], al[tm][2], al[tm][3], sAl + roff);
            }
            #pragma unroll
            for (int tp = 0; tp < 2; tp++) {
                const uint32_t roff = (uint32_t)(wn * 32 + tp * 16 + r16) * TPITCH + kbyte;
                uint32_t r0, r1, r2, r3;
                LDSM4(r0, r1, r2, r3, sBh + roff);
                bh[tp * 2][0] = r0; bh[tp * 2 + 1][0] = r1;
                bh[tp * 2][1] = r2; bh[tp * 2 + 1][1] = r3;
                LDSM4(r0, r1, r2, r3, sBl + roff);
                bl[tp * 2][0] = r0; bl[tp * 2 + 1][0] = r1;
                bl[tp * 2][1] = r2; bl[tp * 2 + 1][1] = r3;
            }
            // main term: fp32 acc
            #pragma unroll
            for (int tm = 0; tm < 2; tm++)
                #pragma unroll
                for (int tn = 0; tn < 4; tn++)
                    MMAF(acc[tm][tn], ah[tm], bh[tn]);
            // corrections: fp16 acc (full-rate path)
            #pragma unroll
            for (int tm = 0; tm < 2; tm++)
                #pragma unroll
                for (int tn = 0; tn < 4; tn++)
                    MMAC(cacc[tm][tn], ah[tm], bl[tn]);
            #pragma unroll
            for (int tm = 0; tm < 2; tm++)
                #pragma unroll
                for (int tn = 0; tn < 4; tn++)
                    MMAC(cacc[tm][tn], al[tm], bh[tn]);
        }
        buf ^= 1;
    }
    #undef ISSUE

    // ---- epilogue: main + corrections + bias (+ feature maps for QKV) ----
    #pragma unroll
    for (int tm = 0; tm < 2; tm++) {
        const int row = m0 + wm * 32 + tm * 16 + (lane >> 2);
        #pragma unroll
        for (int tn = 0; tn < 4; tn++) {
            const int col = n0 + wn * 32 + tn * 8 + (lane & 3) * 2;
            #pragma unroll
            for (int half = 0; half < 2; half++) {
                const int m = row + half * 8;
                __half2 hc = *(__half2*)&cacc[tm][tn][half];
                float v0 = acc[tm][tn][half * 2 + 0] + __half2float(hc.x) + bias[col];
                float v1 = acc[tm][tn][half * 2 + 1] + __half2float(hc.y) + bias[col + 1];
                if (QKV) {
                    if (col < 2 * Dd) {
                        float e0 = v0 > 0.f ? v0 : (expf(v0) - 1.f);
                        float e1 = v1 > 0.f ? v1 : (expf(v1) - 1.f);
                        v0 = e0 + 1.0001f; v1 = e1 + 1.0001f;
                        if (col < Dd) { v0 *= 0.125f; v1 *= 0.125f; }
                    }
                }
                float2 o; o.x = v0; o.y = v1;
                *(float2*)(C + (size_t)m * NTOT + col) = o;
            }
        }
    }
}

// ---------------------------------------------------------------------------
// Chunked linear attention, stage A: per-chunk KV outer-product sums + k sums.
// ---------------------------------------------------------------------------
#define CK_SK 0
#define CK_SV (CL * 68)
#define CK_TOT ((CL * 68 * 2) * 4)     // 69632 bytes

__global__ __launch_bounds__(256)
void chunk_kv()
{
    extern __shared__ float s[];
    float (*sk)[68] = (float(*)[68])(s + CK_SK);
    float (*sv)[68] = (float(*)[68])(s + CK_SV);

    const int blk = blockIdx.x;
    const int bh = blk >> 4, c = blk & 15;
    const int b = bh >> 4, h = bh & 15;
    const float* kbase = g_qkv + ((size_t)(b * Ll + c * CL)) * TD + Dd + h * Ee;
    const float* vbase = kbase + Dd;
    const int tid = threadIdx.x;

    #pragma unroll
    for (int t = 0; t < 8; t++) {
        int id = tid + t * 256;            // 0..2047 = 128 rows x 16 float4
        int i = id >> 4, c4 = (id & 15) * 4;
        *(float4*)&sk[i][c4] = *(const float4*)(kbase + (size_t)i * TD + c4);
        *(float4*)&sv[i][c4] = *(const float4*)(vbase + (size_t)i * TD + c4);
    }
    __syncthreads();

    const int te = tid >> 4, tf = tid & 15;
    const int e0 = te * 4, f0 = tf * 4;
    float acc[4][4] = {};
    float z4[4] = {0.f, 0.f, 0.f, 0.f};

    for (int i = 0; i < CL; i++) {
        float4 k4 = *(float4*)&sk[i][e0];
        float4 v4 = *(float4*)&sv[i][f0];
        float kk[4] = {k4.x, k4.y, k4.z, k4.w};
        float vv[4] = {v4.x, v4.y, v4.z, v4.w};
        #pragma unroll
        for (int r = 0; r < 4; r++) {
            #pragma unroll
            for (int q = 0; q < 4; q++) acc[r][q] = fmaf(kk[r], vv[q], acc[r][q]);
        }
        if (tf == 0) {
            #pragma unroll
            for (int r = 0; r < 4; r++) z4[r] += kk[r];
        }
    }

    float* kvo = g_kv + (size_t)blk * Ee * Ee;
    #pragma unroll
    for (int r = 0; r < 4; r++) {
        float4 o; o.x = acc[r][0]; o.y = acc[r][1]; o.z = acc[r][2]; o.w = acc[r][3];
        *(float4*)&kvo[(e0 + r) * Ee + f0] = o;
    }
    if (tf == 0) {
        float* zo = g_zc + (size_t)blk * Ee;
        #pragma unroll
        for (int r = 0; r < 4; r++) zo[e0 + r] = z4[r];
    }
}

// ---------------------------------------------------------------------------
// Stage B: in-place exclusive prefix over the NC chunks of each (b,h).
// ---------------------------------------------------------------------------
__global__ __launch_bounds__(256)
void prefix_kv()
{
    const int bh = blockIdx.x;
    const int tid = threadIdx.x;
    float* kvb = g_kv + (size_t)bh * NC * Ee * Ee;

    #pragma unroll
    for (int t = 0; t < 16; t++) {
        const int idx = tid + t * 256;
        float run = 0.f;
        #pragma unroll
        for (int c = 0; c < NC; c++) {
            float tmp = kvb[(size_t)c * (Ee * Ee) + idx];
            kvb[(size_t)c * (Ee * Ee) + idx] = run;
            run += tmp;
        }
    }
    if (tid < Ee) {
        float* zb = g_zc + (size_t)bh * NC * Ee;
        float run = 0.f;
        #pragma unroll
        for (int c = 0; c < NC; c++) {
            float tmp = zb[c * Ee + tid];
            zb[c * Ee + tid] = run;
            run += tmp;
        }
    }
}

// ---------------------------------------------------------------------------
// Stage C: per-chunk attention. Epilogue writes fp16 hi/lo splits directly
// to g_ah / g_al (feeds the out-proj MMA).
// ---------------------------------------------------------------------------
#define CA_SQT 0                          // [64][132] Q transposed
#define CA_SKT (64 * 132)                 // [64][132] K transposed
#define CA_SV  (CA_SKT + 64 * 132)        // [128][68] V
#define CA_SA  (CA_SV + 128 * 68)         // [128][132] masked A
#define CA_SSP (CA_SA + 128 * 132)        // [64][68]  S_prev
#define CA_SZP (CA_SSP + 64 * 68)         // [64]      z_prev
#define CA_TOT ((CA_SZP + 64) * 4)        // bytes = 187648

__global__ __launch_bounds__(256)
void chunk_attn()
{
    extern __shared__ float s[];
    const int blk = blockIdx.x;
    const int bh = blk >> 4, c = blk & 15;
    const int b = bh >> 4, h = bh & 15;
    const size_t row0 = (size_t)b * Ll + c * CL;
    const float* qbase = g_qkv + row0 * TD + h * Ee;
    const float* kbase = qbase + Dd;
    const float* vbase = qbase + 2 * Dd;
    const int tid = threadIdx.x;

    // load Q,K transposed; V row-major
    #pragma unroll
    for (int t = 0; t < 8; t++) {
        int id = tid + t * 256;
        int i = id >> 4, e0 = (id & 15) * 4;
        float4 q4 = *(const float4*)(qbase + (size_t)i * TD + e0);
        float4 k4 = *(const float4*)(kbase + (size_t)i * TD + e0);
        float4 v4 = *(const float4*)(vbase + (size_t)i * TD + e0);
        s[CA_SQT + (e0 + 0) * 132 + i] = q4.x;
        s[CA_SQT + (e0 + 1) * 132 + i] = q4.y;
        s[CA_SQT + (e0 + 2) * 132 + i] = q4.z;
        s[CA_SQT + (e0 + 3) * 132 + i] = q4.w;
        s[CA_SKT + (e0 + 0) * 132 + i] = k4.x;
        s[CA_SKT + (e0 + 1) * 132 + i] = k4.y;
        s[CA_SKT + (e0 + 2) * 132 + i] = k4.z;
        s[CA_SKT + (e0 + 3) * 132 + i] = k4.w;
        *(float4*)&s[CA_SV + i * 68 + e0] = v4;
    }
    // load S_prev (exclusive prefix) and z_prev
    {
        const float* kvp = g_kv + (size_t)blk * (Ee * Ee);
        #pragma unroll
        for (int t = 0; t < 4; t++) {
            int id = tid + t * 256;          // 0..1023 = 64x16 float4
            int e = id >> 4, f0 = (id & 15) * 4;
            *(float4*)&s[CA_SSP + e * 68 + f0] = *(const float4*)(kvp + e * Ee + f0);
        }
        if (tid < Ee) s[CA_SZP + tid] = g_zc[(size_t)blk * Ee + tid];
    }
    __syncthreads();

    // Phase 1: masked A = Q K^T
    {
        const int ti = tid >> 4, tj = tid & 15;
        const int i0 = ti * 8, j0 = tj * 8;
        float acc[8][8] = {};
        for (int e = 0; e < Ee; e++) {
            float q8[8], k8[8];
            *(float4*)&q8[0] = *(float4*)&s[CA_SQT + e * 132 + i0];
            *(float4*)&q8[4] = *(float4*)&s[CA_SQT + e * 132 + i0 + 4];
            *(float4*)&k8[0] = *(float4*)&s[CA_SKT + e * 132 + j0];
            *(float4*)&k8[4] = *(float4*)&s[CA_SKT + e * 132 + j0 + 4];
            #pragma unroll
            for (int r = 0; r < 8; r++)
                #pragma unroll
                for (int t = 0; t < 8; t++)
                    acc[r][t] = fmaf(q8[r], k8[t], acc[r][t]);
        }
        #pragma unroll
        for (int r = 0; r < 8; r++)
            #pragma unroll
            for (int t = 0; t < 8; t++) {
                const int i = i0 + r, j = j0 + t;
                s[CA_SA + i * 132 + j] = (j <= i) ? acc[r][t] : 0.f;
            }
    }
    __syncthreads();

    // Phase 2: num = A V + Q S_prev ; den = rowsum(A) + q.z_prev
    {
        const int ti = tid >> 3, tf = tid & 7;
        const int i0 = ti * 4, f0 = tf * 8;
        float acc[4][8] = {};
        float den[4] = {0.f, 0.f, 0.f, 0.f};

        for (int j = 0; j < CL; j++) {
            float a4[4];
            #pragma unroll
            for (int r = 0; r < 4; r++) a4[r] = s[CA_SA + (i0 + r) * 132 + j];
            float v8[8];
            *(float4*)&v8[0] = *(float4*)&s[CA_SV + j * 68 + f0];
            *(float4*)&v8[4] = *(float4*)&s[CA_SV + j * 68 + f0 + 4];
            #pragma unroll
            for (int r = 0; r < 4; r++) {
                den[r] += a4[r];
                #pragma unroll
                for (int t = 0; t < 8; t++)
                    acc[r][t] = fmaf(a4[r], v8[t], acc[r][t]);
            }
        }
        for (int e = 0; e < Ee; e++) {
            float q4[4];
            #pragma unroll
            for (int r = 0; r < 4; r++) q4[r] = s[CA_SQT + e * 132 + i0 + r];
            float s8[8];
            *(float4*)&s8[0] = *(float4*)&s[CA_SSP + e * 68 + f0];
            *(float4*)&s8[4] = *(float4*)&s[CA_SSP + e * 68 + f0 + 4];
            const float zz = s[CA_SZP + e];
            #pragma unroll
            for (int r = 0; r < 4; r++) {
                den[r] = fmaf(q4[r], zz, den[r]);
                #pragma unroll
                for (int t = 0; t < 8; t++)
                    acc[r][t] = fmaf(q4[r], s8[t], acc[r][t]);
            }
        }
        #pragma unroll
        for (int r = 0; r < 4; r++) {
            const float inv = 1.f / (den[r] + 1e-4f);
            const size_t obase = (row0 + i0 + r) * Kdim + h * Ee + f0;
            __half hv[8], lv[8];
            #pragma unroll
            for (int t = 0; t < 8; t++) {
                const float v = acc[r][t] * inv;
                hv[t] = __float2half_rn(v);
                lv[t] = __float2half_rn(v - __half2float(hv[t]));
            }
            *(uint4*)(g_ah + obase) = *(uint4*)hv;
            *(uint4*)(g_al + obase) = *(uint4*)lv;
        }
    }
}

// ---------------------------------------------------------------------------
// In-place LayerNorm over rows of d_out (4096 rows x 1024).
// ---------------------------------------------------------------------------
__global__ __launch_bounds__(256)
void layernorm_inplace(float* __restrict__ out,
                       const float* __restrict__ gamma,
                       const float* __restrict__ beta)
{
    const int row = blockIdx.x;
    float* p = out + (size_t)row * Dd;
    const int tid = threadIdx.x;

    float4 v = ((const float4*)p)[tid];
    float s = v.x + v.y + v.z + v.w;
    float q = v.x * v.x + v.y * v.y + v.z * v.z + v.w * v.w;

    #pragma unroll
    for (int o = 16; o > 0; o >>= 1) {
        s += __shfl_xor_sync(0xffffffffu, s, o);
        q += __shfl_xor_sync(0xffffffffu, q, o);
    }
    __shared__ float ss[8], sqr[8];
    const int w = tid >> 5, lane = tid & 31;
    if (lane == 0) { ss[w] = s; sqr[w] = q; }
    __syncthreads();
    if (w == 0) {
        s = (lane < 8) ? ss[lane] : 0.f;
        q = (lane < 8) ? sqr[lane] : 0.f;
        #pragma unroll
        for (int o = 4; o > 0; o >>= 1) {
            s += __shfl_xor_sync(0xffffffffu, s, o);
            q += __shfl_xor_sync(0xffffffffu, q, o);
        }
        if (lane == 0) { ss[0] = s; sqr[0] = q; }
    }
    __syncthreads();

    const float mu  = ss[0] * (1.f / 1024.f);
    const float var = sqr[0] * (1.f / 1024.f) - mu * mu;
    const float inv = rsqrtf(var + 1e-5f);

    float4 gv = ((const float4*)gamma)[tid];
    float4 bv = ((const float4*)beta)[tid];
    float4 o4;
    o4.x = (v.x - mu) * inv * gv.x + bv.x;
    o4.y = (v.y - mu) * inv * gv.y + bv.y;
    o4.z = (v.z - mu) * inv * gv.z + bv.z;
    o4.w = (v.w - mu) * inv * gv.w + bv.w;
    ((float4*)p)[tid] = o4;
}

// ---------------------------------------------------------------------------
extern "C" void kernel_launch(void* const* d_in, const int* in_sizes, int n_in,
                              void* d_out, int out_size)
{
    const float* x     = (const float*)d_in[0];
    const float* Wqkv  = (const float*)d_in[1];
    const float* bqkv  = (const float*)d_in[2];
    const float* Wout  = (const float*)d_in[3];
    const float* bout  = (const float*)d_in[4];
    const float* gamma = (const float*)d_in[5];
    const float* beta  = (const float*)d_in[6];
    float* out = (float*)d_out;

    cudaFuncSetAttribute(mma_gemm<true>,  cudaFuncAttributeMaxDynamicSharedMemorySize, GSM);
    cudaFuncSetAttribute(mma_gemm<false>, cudaFuncAttributeMaxDynamicSharedMemorySize, GSM);
    cudaFuncSetAttribute(chunk_kv,   cudaFuncAttributeMaxDynamicSharedMemorySize, CK_TOT);
    cudaFuncSetAttribute(chunk_attn, cudaFuncAttributeMaxDynamicSharedMemorySize, CA_TOT);

    __half *xh, *xl, *wqh, *wql, *woh, *wol;
    cudaGetSymbolAddress((void**)&xh,  g_xh);
    cudaGetSymbolAddress((void**)&xl,  g_xl);
    cudaGetSymbolAddress((void**)&wqh, g_wqh);
    cudaGetSymbolAddress((void**)&wql, g_wql);
    cudaGetSymbolAddress((void**)&woh, g_woh);
    cudaGetSymbolAddress((void**)&wol, g_wol);

    // 0) fp16 splits of x and weights
    split_f16<<<(Mrows * Kdim / 4 + 255) / 256, 256>>>(x, xh, xl, Mrows * Kdim / 4);
    split_f16<<<(TD * Kdim / 4 + 255) / 256, 256>>>(Wqkv, wqh, wql, TD * Kdim / 4);
    split_f16<<<(Dd * Kdim / 4 + 255) / 256, 256>>>(Wout, woh, wol, Dd * Kdim / 4);

    // 1) QKV projection (mma.sync fp16 split) + bias + feature maps -> g_qkv
    mma_gemm<true><<<dim3(TD / 128, Mrows / 128), 512, GSM>>>(bqkv, nullptr);

    // 2) Chunked causal linear attention -> g_ah/g_al (fp16 split, fused)
    chunk_kv<<<Bb * Hh * NC, 256, CK_TOT>>>();
    prefix_kv<<<Bb * Hh, 256>>>();
    chunk_attn<<<Bb * Hh * NC, 256, CA_TOT>>>();

    // 3) Output projection (mma.sync fp16 split) + bias -> d_out
    mma_gemm<false><<<dim3(Dd / 128, Mrows / 128), 512, GSM>>>(bout, out);

    // 4) LayerNorm in place on d_out
    layernorm_inplace<<<Mrows, 256>>>(out, gamma, beta);
}

// round 15
// speedup vs baseline: 1.7184x; 1.7184x over previous
#include <cuda_runtime.h>
#include <cuda_fp16.h>
#include <math.h>
#include <stdint.h>

// Problem constants (fixed shapes)
#define Bb 2
#define Ll 2048
#define Dd 1024
#define Hh 16
#define Ee 64
#define TD 3072          // 3*D
#define Mrows 4096       // B*L
#define Kdim 1024
#define CL 128           // chunk length
#define NC 16            // chunks per (b,h) sequence

// ---------------------------------------------------------------------------
// Device scratch (no allocation allowed)
// ---------------------------------------------------------------------------
__device__ float g_qkv[(size_t)Mrows * TD];    // feature-mapped q,k and raw v (fp32)
__device__ float g_kv[(size_t)Bb * Hh * NC * Ee * Ee];  // per-chunk KV sums -> exclusive prefixes
__device__ float g_zc[(size_t)Bb * Hh * NC * Ee];       // per-chunk k sums  -> exclusive prefixes

// fp16 operands (single-term)
__device__ __half g_xh[(size_t)Mrows * Kdim];
__device__ __half g_wqh[(size_t)TD * Kdim];
__device__ __half g_woh[(size_t)Dd * Kdim];
__device__ __half g_ah[(size_t)Mrows * Kdim];   // attention output (written by chunk_attn)

// ---------------------------------------------------------------------------
// PTX helpers (base sm_100 feature set: mma.sync, ldmatrix, cp.async)
// ---------------------------------------------------------------------------
__device__ __forceinline__ uint32_t smem_u32(const void* p) {
    uint32_t a;
    asm("{ .reg .u64 t; cvta.to.shared.u64 t, %1; cvt.u32.u64 %0, t; }" : "=r"(a) : "l"(p));
    return a;
}

#define CP16(dst, src) \
    asm volatile("cp.async.cg.shared.global [%0], [%1], 16;" :: "r"(dst), "l"(src))
#define CP_COMMIT() asm volatile("cp.async.commit_group;" ::: "memory")
#define CP_WAIT0()  asm volatile("cp.async.wait_group 0;" ::: "memory")

#define LDSM4(r0, r1, r2, r3, addr) \
    asm volatile("ldmatrix.sync.aligned.m8n8.x4.shared.b16 {%0,%1,%2,%3}, [%4];" \
        : "=r"(r0), "=r"(r1), "=r"(r2), "=r"(r3) : "r"(addr))

#define MMAF(d, a, b) \
    asm volatile("mma.sync.aligned.m16n8k16.row.col.f32.f16.f16.f32 " \
        "{%0,%1,%2,%3},{%4,%5,%6,%7},{%8,%9},{%0,%1,%2,%3};" \
        : "+f"((d)[0]), "+f"((d)[1]), "+f"((d)[2]), "+f"((d)[3]) \
        : "r"((a)[0]), "r"((a)[1]), "r"((a)[2]), "r"((a)[3]), \
          "r"((b)[0]), "r"((b)[1]))

// ---------------------------------------------------------------------------
// fp32 -> fp16 convert (no lo term)
// ---------------------------------------------------------------------------
__global__ __launch_bounds__(256)
void conv_f16(const float* __restrict__ s, __half* __restrict__ h, int n4) {
    int i = blockIdx.x * 256 + threadIdx.x;
    if (i >= n4) return;
    float4 v = ((const float4*)s)[i];
    __half2 a = __floats2half2_rn(v.x, v.y);
    __half2 b = __floats2half2_rn(v.z, v.w);
    ((__half2*)h)[2 * i]     = a;
    ((__half2*)h)[2 * i + 1] = b;
}

// ---------------------------------------------------------------------------
// mma.sync GEMM: C[M,N] = A[M,K] @ B[N,K]^T + bias (single fp16 term,
// fp32 accumulate). 128x128x32 tile, 256 threads (8 warps 2m x 4n),
// double-buffered cp.async, single barrier per chunk. SMEM = 40 KB.
// ---------------------------------------------------------------------------
#define TPITCH 80
#define TSZ   (128 * TPITCH)
#define GSM   (2 * 2 * TSZ)    // 40960 B

template<bool QKV>
__global__ __launch_bounds__(256)
void mma_gemm(const float* __restrict__ bias, float* __restrict__ Cp)
{
    constexpr int NTOT = QKV ? TD : Dd;
    extern __shared__ char sm[];
    const uint32_t sb = smem_u32(sm);

    const __half* Ap = QKV ? g_xh : g_ah;
    const __half* Bp = QKV ? g_wqh : g_woh;
    float* C = QKV ? g_qkv : Cp;

    const int tid  = threadIdx.x;
    const int lane = tid & 31;
    const int wid  = tid >> 5;
    const int wm   = wid & 1;         // 0..1 (m, 64 rows each)
    const int wn   = wid >> 1;        // 0..3 (n, 32 cols each)
    const int m0   = blockIdx.y * 128;
    const int n0   = blockIdx.x * 128;

    const int lrow = tid >> 2;            // 0..63
    const int lcb  = (tid & 3) * 16;
    const int lce  = (tid & 3) * 8;

    const __half* gsrc[2] = { Ap + (size_t)m0 * Kdim, Bp + (size_t)n0 * Kdim };

    float acc[4][4][4];
    #pragma unroll
    for (int i = 0; i < 4; i++)
        #pragma unroll
        for (int j = 0; j < 4; j++)
            #pragma unroll
            for (int r = 0; r < 4; r++) acc[i][j][r] = 0.f;

    #define ISSUE(buf, kc) do {                                               \
        const int k0_ = (kc) * 32;                                            \
        const uint32_t db_ = sb + (buf) * 2 * TSZ;                            \
        _Pragma("unroll")                                                     \
        for (int t_ = 0; t_ < 2; t_++) {                                      \
            const __half* bp_ = gsrc[t_];                                     \
            uint32_t ds_ = db_ + t_ * TSZ;                                    \
            CP16(ds_ + lrow * TPITCH + lcb,                                   \
                 bp_ + (size_t)lrow * Kdim + k0_ + lce);                      \
            CP16(ds_ + (lrow + 64) * TPITCH + lcb,                            \
                 bp_ + (size_t)(lrow + 64) * Kdim + k0_ + lce);               \
        }                                                                     \
    } while (0)

    ISSUE(0, 0); CP_COMMIT();

    const int r16 = lane & 15;
    const int kb8 = (lane >> 4) * 16;

    int buf = 0;
    for (int kc = 0; kc < Kdim / 32; kc++) {
        CP_WAIT0();
        __syncthreads();
        if (kc + 1 < Kdim / 32) { ISSUE(buf ^ 1, kc + 1); CP_COMMIT(); }

        const uint32_t base = sb + buf * 2 * TSZ;
        const uint32_t sA = base, sB = base + TSZ;

        #pragma unroll
        for (int ks = 0; ks < 2; ks++) {
            const int kbyte = ks * 32 + kb8;
            uint32_t a[4][4], b[4][2];
            #pragma unroll
            for (int tm = 0; tm < 4; tm++) {
                const uint32_t roff = (uint32_t)(wm * 64 + tm * 16 + r16) * TPITCH + kbyte;
                LDSM4(a[tm][0], a[tm][1], a[tm][2], a[tm][3], sA + roff);
            }
            #pragma unroll
            for (int tp = 0; tp < 2; tp++) {
                const uint32_t roff = (uint32_t)(wn * 32 + tp * 16 + r16) * TPITCH + kbyte;
                uint32_t r0, r1, r2, r3;
                LDSM4(r0, r1, r2, r3, sB + roff);
                b[tp * 2][0] = r0; b[tp * 2 + 1][0] = r1;
                b[tp * 2][1] = r2; b[tp * 2 + 1][1] = r3;
            }
            #pragma unroll
            for (int tm = 0; tm < 4; tm++)
                #pragma unroll
                for (int tn = 0; tn < 4; tn++)
                    MMAF(acc[tm][tn], a[tm], b[tn]);
        }
        buf ^= 1;
    }
    #undef ISSUE

    #pragma unroll
    for (int tm = 0; tm < 4; tm++) {
        const int row = m0 + wm * 64 + tm * 16 + (lane >> 2);
        #pragma unroll
        for (int tn = 0; tn < 4; tn++) {
            const int col = n0 + wn * 32 + tn * 8 + (lane & 3) * 2;
            #pragma unroll
            for (int half = 0; half < 2; half++) {
                const int m = row + half * 8;
                float v0 = acc[tm][tn][half * 2 + 0] + bias[col];
                float v1 = acc[tm][tn][half * 2 + 1] + bias[col + 1];
                if (QKV) {
                    if (col < 2 * Dd) {
                        float e0 = v0 > 0.f ? v0 : (expf(v0) - 1.f);
                        float e1 = v1 > 0.f ? v1 : (expf(v1) - 1.f);
                        v0 = e0 + 1.0001f; v1 = e1 + 1.0001f;
                        if (col < Dd) { v0 *= 0.125f; v1 *= 0.125f; }
                    }
                }
                float2 o; o.x = v0; o.y = v1;
                *(float2*)(C + (size_t)m * NTOT + col) = o;
            }
        }
    }
}

// ---------------------------------------------------------------------------
// Chunked linear attention, stage A: per-chunk KV outer-product sums + k sums.
// ---------------------------------------------------------------------------
#define CK_SK 0
#define CK_SV (CL * 68)
#define CK_TOT ((CL * 68 * 2) * 4)     // 69632 bytes

__global__ __launch_bounds__(256)
void chunk_kv()
{
    extern __shared__ float s[];
    float (*sk)[68] = (float(*)[68])(s + CK_SK);
    float (*sv)[68] = (float(*)[68])(s + CK_SV);

    const int blk = blockIdx.x;
    const int bh = blk >> 4, c = blk & 15;
    const int b = bh >> 4, h = bh & 15;
    const float* kbase = g_qkv + ((size_t)(b * Ll + c * CL)) * TD + Dd + h * Ee;
    const float* vbase = kbase + Dd;
    const int tid = threadIdx.x;

    #pragma unroll
    for (int t = 0; t < 8; t++) {
        int id = tid + t * 256;
        int i = id >> 4, c4 = (id & 15) * 4;
        *(float4*)&sk[i][c4] = *(const float4*)(kbase + (size_t)i * TD + c4);
        *(float4*)&sv[i][c4] = *(const float4*)(vbase + (size_t)i * TD + c4);
    }
    __syncthreads();

    const int te = tid >> 4, tf = tid & 15;
    const int e0 = te * 4, f0 = tf * 4;
    float acc[4][4] = {};
    float z4[4] = {0.f, 0.f, 0.f, 0.f};

    for (int i = 0; i < CL; i++) {
        float4 k4 = *(float4*)&sk[i][e0];
        float4 v4 = *(float4*)&sv[i][f0];
        float kk[4] = {k4.x, k4.y, k4.z, k4.w};
        float vv[4] = {v4.x, v4.y, v4.z, v4.w};
        #pragma unroll
        for (int r = 0; r < 4; r++) {
            #pragma unroll
            for (int q = 0; q < 4; q++) acc[r][q] = fmaf(kk[r], vv[q], acc[r][q]);
        }
        if (tf == 0) {
            #pragma unroll
            for (int r = 0; r < 4; r++) z4[r] += kk[r];
        }
    }

    float* kvo = g_kv + (size_t)blk * Ee * Ee;
    #pragma unroll
    for (int r = 0; r < 4; r++) {
        float4 o; o.x = acc[r][0]; o.y = acc[r][1]; o.z = acc[r][2]; o.w = acc[r][3];
        *(float4*)&kvo[(e0 + r) * Ee + f0] = o;
    }
    if (tf == 0) {
        float* zo = g_zc + (size_t)blk * Ee;
        #pragma unroll
        for (int r = 0; r < 4; r++) zo[e0 + r] = z4[r];
    }
}

// ---------------------------------------------------------------------------
// Stage B: in-place exclusive prefix over the NC chunks of each (b,h).
// ---------------------------------------------------------------------------
__global__ __launch_bounds__(256)
void prefix_kv()
{
    const int bh = blockIdx.x;
    const int tid = threadIdx.x;
    float* kvb = g_kv + (size_t)bh * NC * Ee * Ee;

    #pragma unroll
    for (int t = 0; t < 16; t++) {
        const int idx = tid + t * 256;
        float run = 0.f;
        #pragma unroll
        for (int c = 0; c < NC; c++) {
            float tmp = kvb[(size_t)c * (Ee * Ee) + idx];
            kvb[(size_t)c * (Ee * Ee) + idx] = run;
            run += tmp;
        }
    }
    if (tid < Ee) {
        float* zb = g_zc + (size_t)bh * NC * Ee;
        float run = 0.f;
        #pragma unroll
        for (int c = 0; c < NC; c++) {
            float tmp = zb[c * Ee + tid];
            zb[c * Ee + tid] = run;
            run += tmp;
        }
    }
}

// ---------------------------------------------------------------------------
// Stage C: per-chunk attention. Epilogue writes fp16 directly to g_ah.
// ---------------------------------------------------------------------------
#define CA_SQT 0                          // [64][132] Q transposed
#define CA_SKT (64 * 132)                 // [64][132] K transposed
#define CA_SV  (CA_SKT + 64 * 132)        // [128][68] V
#define CA_SA  (CA_SV + 128 * 68)         // [128][132] masked A
#define CA_SSP (CA_SA + 128 * 132)        // [64][68]  S_prev
#define CA_SZP (CA_SSP + 64 * 68)         // [64]      z_prev
#define CA_TOT ((CA_SZP + 64) * 4)        // bytes = 187648

__global__ __launch_bounds__(256)
void chunk_attn()
{
    extern __shared__ float s[];
    const int blk = blockIdx.x;
    const int bh = blk >> 4, c = blk & 15;
    const int b = bh >> 4, h = bh & 15;
    const size_t row0 = (size_t)b * Ll + c * CL;
    const float* qbase = g_qkv + row0 * TD + h * Ee;
    const float* kbase = qbase + Dd;
    const float* vbase = qbase + 2 * Dd;
    const int tid = threadIdx.x;

    #pragma unroll
    for (int t = 0; t < 8; t++) {
        int id = tid + t * 256;
        int i = id >> 4, e0 = (id & 15) * 4;
        float4 q4 = *(const float4*)(qbase + (size_t)i * TD + e0);
        float4 k4 = *(const float4*)(kbase + (size_t)i * TD + e0);
        float4 v4 = *(const float4*)(vbase + (size_t)i * TD + e0);
        s[CA_SQT + (e0 + 0) * 132 + i] = q4.x;
        s[CA_SQT + (e0 + 1) * 132 + i] = q4.y;
        s[CA_SQT + (e0 + 2) * 132 + i] = q4.z;
        s[CA_SQT + (e0 + 3) * 132 + i] = q4.w;
        s[CA_SKT + (e0 + 0) * 132 + i] = k4.x;
        s[CA_SKT + (e0 + 1) * 132 + i] = k4.y;
        s[CA_SKT + (e0 + 2) * 132 + i] = k4.z;
        s[CA_SKT + (e0 + 3) * 132 + i] = k4.w;
        *(float4*)&s[CA_SV + i * 68 + e0] = v4;
    }
    {
        const float* kvp = g_kv + (size_t)blk * (Ee * Ee);
        #pragma unroll
        for (int t = 0; t < 4; t++) {
            int id = tid + t * 256;
            int e = id >> 4, f0 = (id & 15) * 4;
            *(float4*)&s[CA_SSP + e * 68 + f0] = *(const float4*)(kvp + e * Ee + f0);
        }
        if (tid < Ee) s[CA_SZP + tid] = g_zc[(size_t)blk * Ee + tid];
    }
    __syncthreads();

    // Phase 1: masked A = Q K^T
    {
        const int ti = tid >> 4, tj = tid & 15;
        const int i0 = ti * 8, j0 = tj * 8;
        float acc[8][8] = {};
        for (int e = 0; e < Ee; e++) {
            float q8[8], k8[8];
            *(float4*)&q8[0] = *(float4*)&s[CA_SQT + e * 132 + i0];
            *(float4*)&q8[4] = *(float4*)&s[CA_SQT + e * 132 + i0 + 4];
            *(float4*)&k8[0] = *(float4*)&s[CA_SKT + e * 132 + j0];
            *(float4*)&k8[4] = *(float4*)&s[CA_SKT + e * 132 + j0 + 4];
            #pragma unroll
            for (int r = 0; r < 8; r++)
                #pragma unroll
                for (int t = 0; t < 8; t++)
                    acc[r][t] = fmaf(q8[r], k8[t], acc[r][t]);
        }
        #pragma unroll
        for (int r = 0; r < 8; r++)
            #pragma unroll
            for (int t = 0; t < 8; t++) {
                const int i = i0 + r, j = j0 + t;
                s[CA_SA + i * 132 + j] = (j <= i) ? acc[r][t] : 0.f;
            }
    }
    __syncthreads();

    // Phase 2: num = A V + Q S_prev ; den = rowsum(A) + q.z_prev
    {
        const int ti = tid >> 3, tf = tid & 7;
        const int i0 = ti * 4, f0 = tf * 8;
        float acc[4][8] = {};
        float den[4] = {0.f, 0.f, 0.f, 0.f};

        for (int j = 0; j < CL; j++) {
            float a4[4];
            #pragma unroll
            for (int r = 0; r < 4; r++) a4[r] = s[CA_SA + (i0 + r) * 132 + j];
            float v8[8];
            *(float4*)&v8[0] = *(float4*)&s[CA_SV + j * 68 + f0];
            *(float4*)&v8[4] = *(float4*)&s[CA_SV + j * 68 + f0 + 4];
            #pragma unroll
            for (int r = 0; r < 4; r++) {
                den[r] += a4[r];
                #pragma unroll
                for (int t = 0; t < 8; t++)
                    acc[r][t] = fmaf(a4[r], v8[t], acc[r][t]);
            }
        }
        for (int e = 0; e < Ee; e++) {
            float q4[4];
            #pragma unroll
            for (int r = 0; r < 4; r++) q4[r] = s[CA_SQT + e * 132 + i0 + r];
            float s8[8];
            *(float4*)&s8[0] = *(float4*)&s[CA_SSP + e * 68 + f0];
            *(float4*)&s8[4] = *(float4*)&s[CA_SSP + e * 68 + f0 + 4];
            const float zz = s[CA_SZP + e];
            #pragma unroll
            for (int r = 0; r < 4; r++) {
                den[r] = fmaf(q4[r], zz, den[r]);
                #pragma unroll
                for (int t = 0; t < 8; t++)
                    acc[r][t] = fmaf(q4[r], s8[t], acc[r][t]);
            }
        }
        #pragma unroll
        for (int r = 0; r < 4; r++) {
            const float inv = 1.f / (den[r] + 1e-4f);
            const size_t obase = (row0 + i0 + r) * Kdim + h * Ee + f0;
            __half hv[8];
            #pragma unroll
            for (int t = 0; t < 8; t++)
                hv[t] = __float2half_rn(acc[r][t] * inv);
            *(uint4*)(g_ah + obase) = *(uint4*)hv;
        }
    }
}

// ---------------------------------------------------------------------------
// In-place LayerNorm over rows of d_out (4096 rows x 1024).
// ---------------------------------------------------------------------------
__global__ __launch_bounds__(256)
void layernorm_inplace(float* __restrict__ out,
                       const float* __restrict__ gamma,
                       const float* __restrict__ beta)
{
    const int row = blockIdx.x;
    float* p = out + (size_t)row * Dd;
    const int tid = threadIdx.x;

    float4 v = ((const float4*)p)[tid];
    float s = v.x + v.y + v.z + v.w;
    float q = v.x * v.x + v.y * v.y + v.z * v.z + v.w * v.w;

    #pragma unroll
    for (int o = 16; o > 0; o >>= 1) {
        s += __shfl_xor_sync(0xffffffffu, s, o);
        q += __shfl_xor_sync(0xffffffffu, q, o);
    }
    __shared__ float ss[8], sqr[8];
    const int w = tid >> 5, lane = tid & 31;
    if (lane == 0) { ss[w] = s; sqr[w] = q; }
    __syncthreads();
    if (w == 0) {
        s = (lane < 8) ? ss[lane] : 0.f;
        q = (lane < 8) ? sqr[lane] : 0.f;
        #pragma unroll
        for (int o = 4; o > 0; o >>= 1) {
            s += __shfl_xor_sync(0xffffffffu, s, o);
            q += __shfl_xor_sync(0xffffffffu, q, o);
        }
        if (lane == 0) { ss[0] = s; sqr[0] = q; }
    }
    __syncthreads();

    const float mu  = ss[0] * (1.f / 1024.f);
    const float var = sqr[0] * (1.f / 1024.f) - mu * mu;
    const float inv = rsqrtf(var + 1e-5f);

    float4 gv = ((const float4*)gamma)[tid];
    float4 bv = ((const float4*)beta)[tid];
    float4 o4;
    o4.x = (v.x - mu) * inv * gv.x + bv.x;
    o4.y = (v.y - mu) * inv * gv.y + bv.y;
    o4.z = (v.z - mu) * inv * gv.z + bv.z;
    o4.w = (v.w - mu) * inv * gv.w + bv.w;
    ((float4*)p)[tid] = o4;
}

// ---------------------------------------------------------------------------
extern "C" void kernel_launch(void* const* d_in, const int* in_sizes, int n_in,
                              void* d_out, int out_size)
{
    const float* x     = (const float*)d_in[0];
    const float* Wqkv  = (const float*)d_in[1];
    const float* bqkv  = (const float*)d_in[2];
    const float* Wout  = (const float*)d_in[3];
    const float* bout  = (const float*)d_in[4];
    const float* gamma = (const float*)d_in[5];
    const float* beta  = (const float*)d_in[6];
    float* out = (float*)d_out;

    cudaFuncSetAttribute(mma_gemm<true>,  cudaFuncAttributeMaxDynamicSharedMemorySize, GSM);
    cudaFuncSetAttribute(mma_gemm<false>, cudaFuncAttributeMaxDynamicSharedMemorySize, GSM);
    cudaFuncSetAttribute(chunk_kv,   cudaFuncAttributeMaxDynamicSharedMemorySize, CK_TOT);
    cudaFuncSetAttribute(chunk_attn, cudaFuncAttributeMaxDynamicSharedMemorySize, CA_TOT);

    __half *xh, *wqh, *woh;
    cudaGetSymbolAddress((void**)&xh,  g_xh);
    cudaGetSymbolAddress((void**)&wqh, g_wqh);
    cudaGetSymbolAddress((void**)&woh, g_woh);

    // 0) fp16 conversions of x and weights
    conv_f16<<<(Mrows * Kdim / 4 + 255) / 256, 256>>>(x, xh, Mrows * Kdim / 4);
    conv_f16<<<(TD * Kdim / 4 + 255) / 256, 256>>>(Wqkv, wqh, TD * Kdim / 4);
    conv_f16<<<(Dd * Kdim / 4 + 255) / 256, 256>>>(Wout, woh, Dd * Kdim / 4);

    // 1) QKV projection (single-term fp16 mma.sync) + bias + feature maps
    mma_gemm<true><<<dim3(TD / 128, Mrows / 128), 256, GSM>>>(bqkv, nullptr);

    // 2) Chunked causal linear attention -> g_ah (fp16, fused)
    chunk_kv<<<Bb * Hh * NC, 256, CK_TOT>>>();
    prefix_kv<<<Bb * Hh, 256>>>();
    chunk_attn<<<Bb * Hh * NC, 256, CA_TOT>>>();

    // 3) Output projection (single-term fp16 mma.sync) + bias -> d_out
    mma_gemm<false><<<dim3(Dd / 128, Mrows / 128), 256, GSM>>>(bout, out);

    // 4) LayerNorm in place on d_out
    layernorm_inplace<<<Mrows, 256>>>(out, gamma, beta);
}

// round 16
// speedup vs baseline: 1.7927x; 1.0433x over previous
#include <cuda_runtime.h>
#include <cuda_fp16.h>
#include <math.h>
#include <stdint.h>

// Problem constants (fixed shapes)
#define Bb 2
#define Ll 2048
#define Dd 1024
#define Hh 16
#define Ee 64
#define TD 3072          // 3*D
#define Mrows 4096       // B*L
#define Kdim 1024
#define CL 128           // chunk length
#define NC 16            // chunks per (b,h) sequence

// ---------------------------------------------------------------------------
// Device scratch (no allocation allowed)
// ---------------------------------------------------------------------------
__device__ float g_qkv[(size_t)Mrows * TD];    // feature-mapped q,k and raw v (fp32)
__device__ float g_kv[(size_t)Bb * Hh * NC * Ee * Ee];  // per-chunk KV sums -> exclusive prefixes
__device__ float g_zc[(size_t)Bb * Hh * NC * Ee];       // per-chunk k sums  -> exclusive prefixes

// fp16 operands (single-term)
__device__ __half g_xh[(size_t)Mrows * Kdim];
__device__ __half g_wqh[(size_t)TD * Kdim];
__device__ __half g_woh[(size_t)Dd * Kdim];
__device__ __half g_ah[(size_t)Mrows * Kdim];   // attention output (written by chunk_attn)

// ---------------------------------------------------------------------------
// PTX helpers (base sm_100 feature set: mma.sync, ldmatrix, cp.async)
// ---------------------------------------------------------------------------
__device__ __forceinline__ uint32_t smem_u32(const void* p) {
    uint32_t a;
    asm("{ .reg .u64 t; cvta.to.shared.u64 t, %1; cvt.u32.u64 %0, t; }" : "=r"(a) : "l"(p));
    return a;
}

#define CP16(dst, src) \
    asm volatile("cp.async.cg.shared.global [%0], [%1], 16;" :: "r"(dst), "l"(src))
#define CP_COMMIT() asm volatile("cp.async.commit_group;" ::: "memory")
#define CP_WAIT0()  asm volatile("cp.async.wait_group 0;" ::: "memory")

#define LDSM4(r0, r1, r2, r3, addr) \
    asm volatile("ldmatrix.sync.aligned.m8n8.x4.shared.b16 {%0,%1,%2,%3}, [%4];" \
        : "=r"(r0), "=r"(r1), "=r"(r2), "=r"(r3) : "r"(addr))

#define MMAF(d, a, b) \
    asm volatile("mma.sync.aligned.m16n8k16.row.col.f32.f16.f16.f32 " \
        "{%0,%1,%2,%3},{%4,%5,%6,%7},{%8,%9},{%0,%1,%2,%3};" \
        : "+f"((d)[0]), "+f"((d)[1]), "+f"((d)[2]), "+f"((d)[3]) \
        : "r"((a)[0]), "r"((a)[1]), "r"((a)[2]), "r"((a)[3]), \
          "r"((b)[0]), "r"((b)[1]))

// ---------------------------------------------------------------------------
// fp32 -> fp16 convert
// ---------------------------------------------------------------------------
__global__ __launch_bounds__(256)
void conv_f16(const float* __restrict__ s, __half* __restrict__ h, int n4) {
    int i = blockIdx.x * 256 + threadIdx.x;
    if (i >= n4) return;
    float4 v = ((const float4*)s)[i];
    __half2 a = __floats2half2_rn(v.x, v.y);
    __half2 b = __floats2half2_rn(v.z, v.w);
    ((__half2*)h)[2 * i]     = a;
    ((__half2*)h)[2 * i + 1] = b;
}

// ---------------------------------------------------------------------------
// mma.sync GEMM (unchanged from passing R15 version).
// ---------------------------------------------------------------------------
#define TPITCH 80
#define TSZ   (128 * TPITCH)
#define GSM   (2 * 2 * TSZ)    // 40960 B

template<bool QKV>
__global__ __launch_bounds__(256)
void mma_gemm(const float* __restrict__ bias, float* __restrict__ Cp)
{
    constexpr int NTOT = QKV ? TD : Dd;
    extern __shared__ char sm[];
    const uint32_t sb = smem_u32(sm);

    const __half* Ap = QKV ? g_xh : g_ah;
    const __half* Bp = QKV ? g_wqh : g_woh;
    float* C = QKV ? g_qkv : Cp;

    const int tid  = threadIdx.x;
    const int lane = tid & 31;
    const int wid  = tid >> 5;
    const int wm   = wid & 1;
    const int wn   = wid >> 1;
    const int m0   = blockIdx.y * 128;
    const int n0   = blockIdx.x * 128;

    const int lrow = tid >> 2;
    const int lcb  = (tid & 3) * 16;
    const int lce  = (tid & 3) * 8;

    const __half* gsrc[2] = { Ap + (size_t)m0 * Kdim, Bp + (size_t)n0 * Kdim };

    float acc[4][4][4];
    #pragma unroll
    for (int i = 0; i < 4; i++)
        #pragma unroll
        for (int j = 0; j < 4; j++)
            #pragma unroll
            for (int r = 0; r < 4; r++) acc[i][j][r] = 0.f;

    #define ISSUE(buf, kc) do {                                               \
        const int k0_ = (kc) * 32;                                            \
        const uint32_t db_ = sb + (buf) * 2 * TSZ;                            \
        _Pragma("unroll")                                                     \
        for (int t_ = 0; t_ < 2; t_++) {                                      \
            const __half* bp_ = gsrc[t_];                                     \
            uint32_t ds_ = db_ + t_ * TSZ;                                    \
            CP16(ds_ + lrow * TPITCH + lcb,                                   \
                 bp_ + (size_t)lrow * Kdim + k0_ + lce);                      \
            CP16(ds_ + (lrow + 64) * TPITCH + lcb,                            \
                 bp_ + (size_t)(lrow + 64) * Kdim + k0_ + lce);               \
        }                                                                     \
    } while (0)

    ISSUE(0, 0); CP_COMMIT();

    const int r16 = lane & 15;
    const int kb8 = (lane >> 4) * 16;

    int buf = 0;
    for (int kc = 0; kc < Kdim / 32; kc++) {
        CP_WAIT0();
        __syncthreads();
        if (kc + 1 < Kdim / 32) { ISSUE(buf ^ 1, kc + 1); CP_COMMIT(); }

        const uint32_t base = sb + buf * 2 * TSZ;
        const uint32_t sA = base, sB = base + TSZ;

        #pragma unroll
        for (int ks = 0; ks < 2; ks++) {
            const int kbyte = ks * 32 + kb8;
            uint32_t a[4][4], b[4][2];
            #pragma unroll
            for (int tm = 0; tm < 4; tm++) {
                const uint32_t roff = (uint32_t)(wm * 64 + tm * 16 + r16) * TPITCH + kbyte;
                LDSM4(a[tm][0], a[tm][1], a[tm][2], a[tm][3], sA + roff);
            }
            #pragma unroll
            for (int tp = 0; tp < 2; tp++) {
                const uint32_t roff = (uint32_t)(wn * 32 + tp * 16 + r16) * TPITCH + kbyte;
                uint32_t r0, r1, r2, r3;
                LDSM4(r0, r1, r2, r3, sB + roff);
                b[tp * 2][0] = r0; b[tp * 2 + 1][0] = r1;
                b[tp * 2][1] = r2; b[tp * 2 + 1][1] = r3;
            }
            #pragma unroll
            for (int tm = 0; tm < 4; tm++)
                #pragma unroll
                for (int tn = 0; tn < 4; tn++)
                    MMAF(acc[tm][tn], a[tm], b[tn]);
        }
        buf ^= 1;
    }
    #undef ISSUE

    #pragma unroll
    for (int tm = 0; tm < 4; tm++) {
        const int row = m0 + wm * 64 + tm * 16 + (lane >> 2);
        #pragma unroll
        for (int tn = 0; tn < 4; tn++) {
            const int col = n0 + wn * 32 + tn * 8 + (lane & 3) * 2;
            #pragma unroll
            for (int half = 0; half < 2; half++) {
                const int m = row + half * 8;
                float v0 = acc[tm][tn][half * 2 + 0] + bias[col];
                float v1 = acc[tm][tn][half * 2 + 1] + bias[col + 1];
                if (QKV) {
                    if (col < 2 * Dd) {
                        float e0 = v0 > 0.f ? v0 : (expf(v0) - 1.f);
                        float e1 = v1 > 0.f ? v1 : (expf(v1) - 1.f);
                        v0 = e0 + 1.0001f; v1 = e1 + 1.0001f;
                        if (col < Dd) { v0 *= 0.125f; v1 *= 0.125f; }
                    }
                }
                float2 o; o.x = v0; o.y = v1;
                *(float2*)(C + (size_t)m * NTOT + col) = o;
            }
        }
    }
}

// ---------------------------------------------------------------------------
// Chunked linear attention, stage A: per-chunk KV outer-product sums + k sums.
// ---------------------------------------------------------------------------
#define CK_SK 0
#define CK_SV (CL * 68)
#define CK_TOT ((CL * 68 * 2) * 4)     // 69632 bytes

__global__ __launch_bounds__(256)
void chunk_kv()
{
    extern __shared__ float s[];
    float (*sk)[68] = (float(*)[68])(s + CK_SK);
    float (*sv)[68] = (float(*)[68])(s + CK_SV);

    const int blk = blockIdx.x;
    const int bh = blk >> 4, c = blk & 15;
    const int b = bh >> 4, h = bh & 15;
    const float* kbase = g_qkv + ((size_t)(b * Ll + c * CL)) * TD + Dd + h * Ee;
    const float* vbase = kbase + Dd;
    const int tid = threadIdx.x;

    #pragma unroll
    for (int t = 0; t < 8; t++) {
        int id = tid + t * 256;
        int i = id >> 4, c4 = (id & 15) * 4;
        *(float4*)&sk[i][c4] = *(const float4*)(kbase + (size_t)i * TD + c4);
        *(float4*)&sv[i][c4] = *(const float4*)(vbase + (size_t)i * TD + c4);
    }
    __syncthreads();

    const int te = tid >> 4, tf = tid & 15;
    const int e0 = te * 4, f0 = tf * 4;
    float acc[4][4] = {};
    float z4[4] = {0.f, 0.f, 0.f, 0.f};

    for (int i = 0; i < CL; i++) {
        float4 k4 = *(float4*)&sk[i][e0];
        float4 v4 = *(float4*)&sv[i][f0];
        float kk[4] = {k4.x, k4.y, k4.z, k4.w};
        float vv[4] = {v4.x, v4.y, v4.z, v4.w};
        #pragma unroll
        for (int r = 0; r < 4; r++) {
            #pragma unroll
            for (int q = 0; q < 4; q++) acc[r][q] = fmaf(kk[r], vv[q], acc[r][q]);
        }
        if (tf == 0) {
            #pragma unroll
            for (int r = 0; r < 4; r++) z4[r] += kk[r];
        }
    }

    float* kvo = g_kv + (size_t)blk * Ee * Ee;
    #pragma unroll
    for (int r = 0; r < 4; r++) {
        float4 o; o.x = acc[r][0]; o.y = acc[r][1]; o.z = acc[r][2]; o.w = acc[r][3];
        *(float4*)&kvo[(e0 + r) * Ee + f0] = o;
    }
    if (tf == 0) {
        float* zo = g_zc + (size_t)blk * Ee;
        #pragma unroll
        for (int r = 0; r < 4; r++) zo[e0 + r] = z4[r];
    }
}

// ---------------------------------------------------------------------------
// Stage B: in-place exclusive prefix over the NC chunks of each (b,h).
// ---------------------------------------------------------------------------
__global__ __launch_bounds__(256)
void prefix_kv()
{
    const int bh = blockIdx.x;
    const int tid = threadIdx.x;
    float* kvb = g_kv + (size_t)bh * NC * Ee * Ee;

    #pragma unroll
    for (int t = 0; t < 16; t++) {
        const int idx = tid + t * 256;
        float run = 0.f;
        #pragma unroll
        for (int c = 0; c < NC; c++) {
            float tmp = kvb[(size_t)c * (Ee * Ee) + idx];
            kvb[(size_t)c * (Ee * Ee) + idx] = run;
            run += tmp;
        }
    }
    if (tid < Ee) {
        float* zb = g_zc + (size_t)bh * NC * Ee;
        float run = 0.f;
        #pragma unroll
        for (int c = 0; c < NC; c++) {
            float tmp = zb[c * Ee + tid];
            zb[c * Ee + tid] = run;
            run += tmp;
        }
    }
}

// ---------------------------------------------------------------------------
// Stage C: per-chunk attention, 512 threads (16 warps; smem is the 1-block/SM
// limiter so extra warps are free latency hiding). Same fp32 math, same
// per-element FMA order as the 256-thread version.
// ---------------------------------------------------------------------------
#define CA_SQT 0                          // [64][132] Q transposed
#define CA_SKT (64 * 132)                 // [64][132] K transposed
#define CA_SV  (CA_SKT + 64 * 132)        // [128][68] V
#define CA_SA  (CA_SV + 128 * 68)         // [128][132] masked A
#define CA_SSP (CA_SA + 128 * 132)        // [64][68]  S_prev
#define CA_SZP (CA_SSP + 64 * 68)         // [64]      z_prev
#define CA_TOT ((CA_SZP + 64) * 4)        // bytes = 187648

__global__ __launch_bounds__(512)
void chunk_attn()
{
    extern __shared__ float s[];
    const int blk = blockIdx.x;
    const int bh = blk >> 4, c = blk & 15;
    const int b = bh >> 4, h = bh & 15;
    const size_t row0 = (size_t)b * Ll + c * CL;
    const float* qbase = g_qkv + row0 * TD + h * Ee;
    const float* kbase = qbase + Dd;
    const float* vbase = qbase + 2 * Dd;
    const int tid = threadIdx.x;

    // load Q,K transposed; V row-major (2048 float4 slots over 512 threads)
    #pragma unroll
    for (int t = 0; t < 4; t++) {
        int id = tid + t * 512;
        int i = id >> 4, e0 = (id & 15) * 4;
        float4 q4 = *(const float4*)(qbase + (size_t)i * TD + e0);
        float4 k4 = *(const float4*)(kbase + (size_t)i * TD + e0);
        float4 v4 = *(const float4*)(vbase + (size_t)i * TD + e0);
        s[CA_SQT + (e0 + 0) * 132 + i] = q4.x;
        s[CA_SQT + (e0 + 1) * 132 + i] = q4.y;
        s[CA_SQT + (e0 + 2) * 132 + i] = q4.z;
        s[CA_SQT + (e0 + 3) * 132 + i] = q4.w;
        s[CA_SKT + (e0 + 0) * 132 + i] = k4.x;
        s[CA_SKT + (e0 + 1) * 132 + i] = k4.y;
        s[CA_SKT + (e0 + 2) * 132 + i] = k4.z;
        s[CA_SKT + (e0 + 3) * 132 + i] = k4.w;
        *(float4*)&s[CA_SV + i * 68 + e0] = v4;
    }
    // load S_prev and z_prev (1024 float4 slots over 512 threads)
    {
        const float* kvp = g_kv + (size_t)blk * (Ee * Ee);
        #pragma unroll
        for (int t = 0; t < 2; t++) {
            int id = tid + t * 512;
            int e = id >> 4, f0 = (id & 15) * 4;
            *(float4*)&s[CA_SSP + e * 68 + f0] = *(const float4*)(kvp + e * Ee + f0);
        }
        if (tid < Ee) s[CA_SZP + tid] = g_zc[(size_t)blk * Ee + tid];
    }
    __syncthreads();

    // Phase 1: masked A = Q K^T. 512 threads: 8 rows x 4 cols per thread.
    {
        const int ti = tid >> 5, tj = tid & 31;
        const int i0 = ti * 8, j0 = tj * 4;
        float acc[8][4] = {};
        for (int e = 0; e < Ee; e++) {
            float q8[8], k4[4];
            *(float4*)&q8[0] = *(float4*)&s[CA_SQT + e * 132 + i0];
            *(float4*)&q8[4] = *(float4*)&s[CA_SQT + e * 132 + i0 + 4];
            *(float4*)&k4[0] = *(float4*)&s[CA_SKT + e * 132 + j0];
            #pragma unroll
            for (int r = 0; r < 8; r++)
                #pragma unroll
                for (int t = 0; t < 4; t++)
                    acc[r][t] = fmaf(q8[r], k4[t], acc[r][t]);
        }
        #pragma unroll
        for (int r = 0; r < 8; r++)
            #pragma unroll
            for (int t = 0; t < 4; t++) {
                const int i = i0 + r, j = j0 + t;
                s[CA_SA + i * 132 + j] = (j <= i) ? acc[r][t] : 0.f;
            }
    }
    __syncthreads();

    // Phase 2: num = A V + Q S_prev ; den = rowsum(A) + q.z_prev
    // 512 threads: 4 rows x 4 f-cols per thread.
    {
        const int ti = tid >> 4, tf = tid & 15;
        const int i0 = ti * 4, f0 = tf * 4;
        float acc[4][4] = {};
        float den[4] = {0.f, 0.f, 0.f, 0.f};

        for (int j = 0; j < CL; j++) {
            float a4[4];
            #pragma unroll
            for (int r = 0; r < 4; r++) a4[r] = s[CA_SA + (i0 + r) * 132 + j];
            float v4[4];
            *(float4*)&v4[0] = *(float4*)&s[CA_SV + j * 68 + f0];
            #pragma unroll
            for (int r = 0; r < 4; r++) {
                den[r] += a4[r];
                #pragma unroll
                for (int t = 0; t < 4; t++)
                    acc[r][t] = fmaf(a4[r], v4[t], acc[r][t]);
            }
        }
        for (int e = 0; e < Ee; e++) {
            float q4[4];
            #pragma unroll
            for (int r = 0; r < 4; r++) q4[r] = s[CA_SQT + e * 132 + i0 + r];
            float s4[4];
            *(float4*)&s4[0] = *(float4*)&s[CA_SSP + e * 68 + f0];
            const float zz = s[CA_SZP + e];
            #pragma unroll
            for (int r = 0; r < 4; r++) {
                den[r] = fmaf(q4[r], zz, den[r]);
                #pragma unroll
                for (int t = 0; t < 4; t++)
                    acc[r][t] = fmaf(q4[r], s4[t], acc[r][t]);
            }
        }
        #pragma unroll
        for (int r = 0; r < 4; r++) {
            const float inv = 1.f / (den[r] + 1e-4f);
            const size_t obase = (row0 + i0 + r) * Kdim + h * Ee + f0;
            __half hv[4];
            #pragma unroll
            for (int t = 0; t < 4; t++)
                hv[t] = __float2half_rn(acc[r][t] * inv);
            *(uint2*)(g_ah + obase) = *(uint2*)hv;
        }
    }
}

// ---------------------------------------------------------------------------
// In-place LayerNorm over rows of d_out (4096 rows x 1024).
// ---------------------------------------------------------------------------
__global__ __launch_bounds__(256)
void layernorm_inplace(float* __restrict__ out,
                       const float* __restrict__ gamma,
                       const float* __restrict__ beta)
{
    const int row = blockIdx.x;
    float* p = out + (size_t)row * Dd;
    const int tid = threadIdx.x;

    float4 v = ((const float4*)p)[tid];
    float s = v.x + v.y + v.z + v.w;
    float q = v.x * v.x + v.y * v.y + v.z * v.z + v.w * v.w;

    #pragma unroll
    for (int o = 16; o > 0; o >>= 1) {
        s += __shfl_xor_sync(0xffffffffu, s, o);
        q += __shfl_xor_sync(0xffffffffu, q, o);
    }
    __shared__ float ss[8], sqr[8];
    const int w = tid >> 5, lane = tid & 31;
    if (lane == 0) { ss[w] = s; sqr[w] = q; }
    __syncthreads();
    if (w == 0) {
        s = (lane < 8) ? ss[lane] : 0.f;
        q = (lane < 8) ? sqr[lane] : 0.f;
        #pragma unroll
        for (int o = 4; o > 0; o >>= 1) {
            s += __shfl_xor_sync(0xffffffffu, s, o);
            q += __shfl_xor_sync(0xffffffffu, q, o);
        }
        if (lane == 0) { ss[0] = s; sqr[0] = q; }
    }
    __syncthreads();

    const float mu  = ss[0] * (1.f / 1024.f);
    const float var = sqr[0] * (1.f / 1024.f) - mu * mu;
    const float inv = rsqrtf(var + 1e-5f);

    float4 gv = ((const float4*)gamma)[tid];
    float4 bv = ((const float4*)beta)[tid];
    float4 o4;
    o4.x = (v.x - mu) * inv * gv.x + bv.x;
    o4.y = (v.y - mu) * inv * gv.y + bv.y;
    o4.z = (v.z - mu) * inv * gv.z + bv.z;
    o4.w = (v.w - mu) * inv * gv.w + bv.w;
    ((float4*)p)[tid] = o4;
}

// ---------------------------------------------------------------------------
extern "C" void kernel_launch(void* const* d_in, const int* in_sizes, int n_in,
                              void* d_out, int out_size)
{
    const float* x     = (const float*)d_in[0];
    const float* Wqkv  = (const float*)d_in[1];
    const float* bqkv  = (const float*)d_in[2];
    const float* Wout  = (const float*)d_in[3];
    const float* bout  = (const float*)d_in[4];
    const float* gamma = (const float*)d_in[5];
    const float* beta  = (const float*)d_in[6];
    float* out = (float*)d_out;

    cudaFuncSetAttribute(mma_gemm<true>,  cudaFuncAttributeMaxDynamicSharedMemorySize, GSM);
    cudaFuncSetAttribute(mma_gemm<false>, cudaFuncAttributeMaxDynamicSharedMemorySize, GSM);
    cudaFuncSetAttribute(chunk_kv,   cudaFuncAttributeMaxDynamicSharedMemorySize, CK_TOT);
    cudaFuncSetAttribute(chunk_attn, cudaFuncAttributeMaxDynamicSharedMemorySize, CA_TOT);

    __half *xh, *wqh, *woh;
    cudaGetSymbolAddress((void**)&xh,  g_xh);
    cudaGetSymbolAddress((void**)&wqh, g_wqh);
    cudaGetSymbolAddress((void**)&woh, g_woh);

    // 0) fp16 conversions of x and weights
    conv_f16<<<(Mrows * Kdim / 4 + 255) / 256, 256>>>(x, xh, Mrows * Kdim / 4);
    conv_f16<<<(TD * Kdim / 4 + 255) / 256, 256>>>(Wqkv, wqh, TD * Kdim / 4);
    conv_f16<<<(Dd * Kdim / 4 + 255) / 256, 256>>>(Wout, woh, Dd * Kdim / 4);

    // 1) QKV projection (single-term fp16 mma.sync) + bias + feature maps
    mma_gemm<true><<<dim3(TD / 128, Mrows / 128), 256, GSM>>>(bqkv, nullptr);

    // 2) Chunked causal linear attention -> g_ah (fp16, fused)
    chunk_kv<<<Bb * Hh * NC, 256, CK_TOT>>>();
    prefix_kv<<<Bb * Hh, 256>>>();
    chunk_attn<<<Bb * Hh * NC, 512, CA_TOT>>>();

    // 3) Output projection (single-term fp16 mma.sync) + bias -> d_out
    mma_gemm<false><<<dim3(Dd / 128, Mrows / 128), 256, GSM>>>(bout, out);

    // 4) LayerNorm in place on d_out
    layernorm_inplace<<<Mrows, 256>>>(out, gamma, beta);
}

// round 17
// speedup vs baseline: 1.8999x; 1.0598x over previous
#include <cuda_runtime.h>
#include <cuda_fp16.h>
#include <math.h>
#include <stdint.h>

// Problem constants (fixed shapes)
#define Bb 2
#define Ll 2048
#define Dd 1024
#define Hh 16
#define Ee 64
#define TD 3072          // 3*D
#define Mrows 4096       // B*L
#define Kdim 1024
#define CL 128           // chunk length
#define NC 16            // chunks per (b,h) sequence

// ---------------------------------------------------------------------------
// Device scratch (no allocation allowed)
// ---------------------------------------------------------------------------
__device__ float g_qkv[(size_t)Mrows * TD];    // feature-mapped q,k and raw v (fp32)
__device__ float g_kv[(size_t)Bb * Hh * NC * Ee * Ee];  // per-chunk KV sums -> exclusive prefixes
__device__ float g_zc[(size_t)Bb * Hh * NC * Ee];       // per-chunk k sums  -> exclusive prefixes

// fp16 operands (single-term)
__device__ __half g_xh[(size_t)Mrows * Kdim];
__device__ __half g_wqh[(size_t)TD * Kdim];
__device__ __half g_woh[(size_t)Dd * Kdim];
__device__ __half g_ah[(size_t)Mrows * Kdim];   // attention output (written by chunk_attn)

// ---------------------------------------------------------------------------
// PTX helpers (base sm_100 feature set: mma.sync, ldmatrix, cp.async)
// ---------------------------------------------------------------------------
__device__ __forceinline__ uint32_t smem_u32(const void* p) {
    uint32_t a;
    asm("{ .reg .u64 t; cvta.to.shared.u64 t, %1; cvt.u32.u64 %0, t; }" : "=r"(a) : "l"(p));
    return a;
}

#define CP16(dst, src) \
    asm volatile("cp.async.cg.shared.global [%0], [%1], 16;" :: "r"(dst), "l"(src))
#define CP_COMMIT() asm volatile("cp.async.commit_group;" ::: "memory")
#define CP_WAIT0()  asm volatile("cp.async.wait_group 0;" ::: "memory")

#define LDSM4(r0, r1, r2, r3, addr) \
    asm volatile("ldmatrix.sync.aligned.m8n8.x4.shared.b16 {%0,%1,%2,%3}, [%4];" \
        : "=r"(r0), "=r"(r1), "=r"(r2), "=r"(r3) : "r"(addr))

#define MMAF(d, a, b) \
    asm volatile("mma.sync.aligned.m16n8k16.row.col.f32.f16.f16.f32 " \
        "{%0,%1,%2,%3},{%4,%5,%6,%7},{%8,%9},{%0,%1,%2,%3};" \
        : "+f"((d)[0]), "+f"((d)[1]), "+f"((d)[2]), "+f"((d)[3]) \
        : "r"((a)[0]), "r"((a)[1]), "r"((a)[2]), "r"((a)[3]), \
          "r"((b)[0]), "r"((b)[1]))

// ---------------------------------------------------------------------------
// fp32 -> fp16 convert, all three tensors in ONE launch (grid dispatch)
// ---------------------------------------------------------------------------
#define NX  (Mrows * Kdim / 4)    // 1048576 quads
#define NWQ (TD * Kdim / 4)       // 786432
#define NWO (Dd * Kdim / 4)       // 262144

__global__ __launch_bounds__(256)
void conv_f16_all(const float* __restrict__ x, const float* __restrict__ wq,
                  const float* __restrict__ wo) {
    int i = blockIdx.x * 256 + threadIdx.x;
    const float* s;
    __half* h;
    int j;
    if (i < NX)             { s = x;  h = g_xh;  j = i; }
    else if (i < NX + NWQ)  { s = wq; h = g_wqh; j = i - NX; }
    else if (i < NX + NWQ + NWO) { s = wo; h = g_woh; j = i - NX - NWQ; }
    else return;
    float4 v = ((const float4*)s)[j];
    ((__half2*)h)[2 * j]     = __floats2half2_rn(v.x, v.y);
    ((__half2*)h)[2 * j + 1] = __floats2half2_rn(v.z, v.w);
}

// ---------------------------------------------------------------------------
// mma.sync GEMM: single fp16 term, fp32 accumulate. 128x128x64 tile
// (BK=64: 16 pipeline iters, 64 MMAs per barrier). 256 threads (8 warps
// 2m x 4n), double-buffered cp.async, single barrier per chunk.
// TPITCH=144: 16B-aligned, ldsm conflict-free (8-row start banks 0,4,..28).
// ---------------------------------------------------------------------------
#define TPITCH 144
#define TSZ   (128 * TPITCH)   // 18432 B
#define GSM   (2 * 2 * TSZ)    // 73728 B

template<bool QKV>
__global__ __launch_bounds__(256)
void mma_gemm(const float* __restrict__ bias, float* __restrict__ Cp)
{
    constexpr int NTOT = QKV ? TD : Dd;
    extern __shared__ char sm[];
    const uint32_t sb = smem_u32(sm);

    const __half* Ap = QKV ? g_xh : g_ah;
    const __half* Bp = QKV ? g_wqh : g_woh;
    float* C = QKV ? g_qkv : Cp;

    const int tid  = threadIdx.x;
    const int lane = tid & 31;
    const int wid  = tid >> 5;
    const int wm   = wid & 1;         // 0..1 (m, 64 rows each)
    const int wn   = wid >> 1;        // 0..3 (n, 32 cols each)
    const int m0   = blockIdx.y * 128;
    const int n0   = blockIdx.x * 128;

    // loader coords: per tile 128 rows x 8 x16B; thread covers 4 rows
    const int lrow = tid >> 3;            // 0..31
    const int lcb  = (tid & 7) * 16;      // byte col in smem row
    const int lce  = (tid & 7) * 8;       // element col in gmem row

    const __half* gsrc[2] = { Ap + (size_t)m0 * Kdim, Bp + (size_t)n0 * Kdim };

    float acc[4][4][4];
    #pragma unroll
    for (int i = 0; i < 4; i++)
        #pragma unroll
        for (int j = 0; j < 4; j++)
            #pragma unroll
            for (int r = 0; r < 4; r++) acc[i][j][r] = 0.f;

    #define ISSUE(buf, kc) do {                                               \
        const int k0_ = (kc) * 64;                                            \
        const uint32_t db_ = sb + (buf) * 2 * TSZ;                            \
        _Pragma("unroll")                                                     \
        for (int t_ = 0; t_ < 2; t_++) {                                      \
            const __half* bp_ = gsrc[t_];                                     \
            uint32_t ds_ = db_ + t_ * TSZ;                                    \
            _Pragma("unroll")                                                 \
            for (int r_ = 0; r_ < 4; r_++) {                                  \
                CP16(ds_ + (lrow + r_ * 32) * TPITCH + lcb,                   \
                     bp_ + (size_t)(lrow + r_ * 32) * Kdim + k0_ + lce);      \
            }                                                                 \
        }                                                                     \
    } while (0)

    ISSUE(0, 0); CP_COMMIT();

    const int r16 = lane & 15;
    const int kb8 = (lane >> 4) * 16;

    int buf = 0;
    for (int kc = 0; kc < Kdim / 64; kc++) {
        CP_WAIT0();
        __syncthreads();
        if (kc + 1 < Kdim / 64) { ISSUE(buf ^ 1, kc + 1); CP_COMMIT(); }

        const uint32_t base = sb + buf * 2 * TSZ;
        const uint32_t sA = base, sB = base + TSZ;

        #pragma unroll
        for (int ks = 0; ks < 4; ks++) {
            const int kbyte = ks * 32 + kb8;
            uint32_t a[4][4], b[4][2];
            #pragma unroll
            for (int tm = 0; tm < 4; tm++) {
                const uint32_t roff = (uint32_t)(wm * 64 + tm * 16 + r16) * TPITCH + kbyte;
                LDSM4(a[tm][0], a[tm][1], a[tm][2], a[tm][3], sA + roff);
            }
            #pragma unroll
            for (int tp = 0; tp < 2; tp++) {
                const uint32_t roff = (uint32_t)(wn * 32 + tp * 16 + r16) * TPITCH + kbyte;
                uint32_t r0, r1, r2, r3;
                LDSM4(r0, r1, r2, r3, sB + roff);
                b[tp * 2][0] = r0; b[tp * 2 + 1][0] = r1;
                b[tp * 2][1] = r2; b[tp * 2 + 1][1] = r3;
            }
            #pragma unroll
            for (int tm = 0; tm < 4; tm++)
                #pragma unroll
                for (int tn = 0; tn < 4; tn++)
                    MMAF(acc[tm][tn], a[tm], b[tn]);
        }
        buf ^= 1;
    }
    #undef ISSUE

    #pragma unroll
    for (int tm = 0; tm < 4; tm++) {
        const int row = m0 + wm * 64 + tm * 16 + (lane >> 2);
        #pragma unroll
        for (int tn = 0; tn < 4; tn++) {
            const int col = n0 + wn * 32 + tn * 8 + (lane & 3) * 2;
            #pragma unroll
            for (int half = 0; half < 2; half++) {
                const int m = row + half * 8;
                float v0 = acc[tm][tn][half * 2 + 0] + bias[col];
                float v1 = acc[tm][tn][half * 2 + 1] + bias[col + 1];
                if (QKV) {
                    if (col < 2 * Dd) {
                        float e0 = v0 > 0.f ? v0 : (expf(v0) - 1.f);
                        float e1 = v1 > 0.f ? v1 : (expf(v1) - 1.f);
                        v0 = e0 + 1.0001f; v1 = e1 + 1.0001f;
                        if (col < Dd) { v0 *= 0.125f; v1 *= 0.125f; }
                    }
                }
                float2 o; o.x = v0; o.y = v1;
                *(float2*)(C + (size_t)m * NTOT + col) = o;
            }
        }
    }
}

// ---------------------------------------------------------------------------
// Chunked linear attention, stage A: per-chunk KV outer-product sums + k sums.
// ---------------------------------------------------------------------------
#define CK_SK 0
#define CK_SV (CL * 68)
#define CK_TOT ((CL * 68 * 2) * 4)     // 69632 bytes

__global__ __launch_bounds__(256)
void chunk_kv()
{
    extern __shared__ float s[];
    float (*sk)[68] = (float(*)[68])(s + CK_SK);
    float (*sv)[68] = (float(*)[68])(s + CK_SV);

    const int blk = blockIdx.x;
    const int bh = blk >> 4, c = blk & 15;
    const int b = bh >> 4, h = bh & 15;
    const float* kbase = g_qkv + ((size_t)(b * Ll + c * CL)) * TD + Dd + h * Ee;
    const float* vbase = kbase + Dd;
    const int tid = threadIdx.x;

    #pragma unroll
    for (int t = 0; t < 8; t++) {
        int id = tid + t * 256;
        int i = id >> 4, c4 = (id & 15) * 4;
        *(float4*)&sk[i][c4] = *(const float4*)(kbase + (size_t)i * TD + c4);
        *(float4*)&sv[i][c4] = *(const float4*)(vbase + (size_t)i * TD + c4);
    }
    __syncthreads();

    const int te = tid >> 4, tf = tid & 15;
    const int e0 = te * 4, f0 = tf * 4;
    float acc[4][4] = {};
    float z4[4] = {0.f, 0.f, 0.f, 0.f};

    for (int i = 0; i < CL; i++) {
        float4 k4 = *(float4*)&sk[i][e0];
        float4 v4 = *(float4*)&sv[i][f0];
        float kk[4] = {k4.x, k4.y, k4.z, k4.w};
        float vv[4] = {v4.x, v4.y, v4.z, v4.w};
        #pragma unroll
        for (int r = 0; r < 4; r++) {
            #pragma unroll
            for (int q = 0; q < 4; q++) acc[r][q] = fmaf(kk[r], vv[q], acc[r][q]);
        }
        if (tf == 0) {
            #pragma unroll
            for (int r = 0; r < 4; r++) z4[r] += kk[r];
        }
    }

    float* kvo = g_kv + (size_t)blk * Ee * Ee;
    #pragma unroll
    for (int r = 0; r < 4; r++) {
        float4 o; o.x = acc[r][0]; o.y = acc[r][1]; o.z = acc[r][2]; o.w = acc[r][3];
        *(float4*)&kvo[(e0 + r) * Ee + f0] = o;
    }
    if (tf == 0) {
        float* zo = g_zc + (size_t)blk * Ee;
        #pragma unroll
        for (int r = 0; r < 4; r++) zo[e0 + r] = z4[r];
    }
}

// ---------------------------------------------------------------------------
// Stage B: in-place exclusive prefix over the NC chunks of each (b,h).
// ---------------------------------------------------------------------------
__global__ __launch_bounds__(256)
void prefix_kv()
{
    const int bh = blockIdx.x;
    const int tid = threadIdx.x;
    float* kvb = g_kv + (size_t)bh * NC * Ee * Ee;

    #pragma unroll
    for (int t = 0; t < 16; t++) {
        const int idx = tid + t * 256;
        float run = 0.f;
        #pragma unroll
        for (int c = 0; c < NC; c++) {
            float tmp = kvb[(size_t)c * (Ee * Ee) + idx];
            kvb[(size_t)c * (Ee * Ee) + idx] = run;
            run += tmp;
        }
    }
    if (tid < Ee) {
        float* zb = g_zc + (size_t)bh * NC * Ee;
        float run = 0.f;
        #pragma unroll
        for (int c = 0; c < NC; c++) {
            float tmp = zb[c * Ee + tid];
            zb[c * Ee + tid] = run;
            run += tmp;
        }
    }
}

// ---------------------------------------------------------------------------
// Stage C: per-chunk attention, 512 threads (unchanged from passing R16).
// ---------------------------------------------------------------------------
#define CA_SQT 0                          // [64][132] Q transposed
#define CA_SKT (64 * 132)                 // [64][132] K transposed
#define CA_SV  (CA_SKT + 64 * 132)        // [128][68] V
#define CA_SA  (CA_SV + 128 * 68)         // [128][132] masked A
#define CA_SSP (CA_SA + 128 * 132)        // [64][68]  S_prev
#define CA_SZP (CA_SSP + 64 * 68)         // [64]      z_prev
#define CA_TOT ((CA_SZP + 64) * 4)        // bytes = 187648

__global__ __launch_bounds__(512)
void chunk_attn()
{
    extern __shared__ float s[];
    const int blk = blockIdx.x;
    const int bh = blk >> 4, c = blk & 15;
    const int b = bh >> 4, h = bh & 15;
    const size_t row0 = (size_t)b * Ll + c * CL;
    const float* qbase = g_qkv + row0 * TD + h * Ee;
    const float* kbase = qbase + Dd;
    const float* vbase = qbase + 2 * Dd;
    const int tid = threadIdx.x;

    #pragma unroll
    for (int t = 0; t < 4; t++) {
        int id = tid + t * 512;
        int i = id >> 4, e0 = (id & 15) * 4;
        float4 q4 = *(const float4*)(qbase + (size_t)i * TD + e0);
        float4 k4 = *(const float4*)(kbase + (size_t)i * TD + e0);
        float4 v4 = *(const float4*)(vbase + (size_t)i * TD + e0);
        s[CA_SQT + (e0 + 0) * 132 + i] = q4.x;
        s[CA_SQT + (e0 + 1) * 132 + i] = q4.y;
        s[CA_SQT + (e0 + 2) * 132 + i] = q4.z;
        s[CA_SQT + (e0 + 3) * 132 + i] = q4.w;
        s[CA_SKT + (e0 + 0) * 132 + i] = k4.x;
        s[CA_SKT + (e0 + 1) * 132 + i] = k4.y;
        s[CA_SKT + (e0 + 2) * 132 + i] = k4.z;
        s[CA_SKT + (e0 + 3) * 132 + i] = k4.w;
        *(float4*)&s[CA_SV + i * 68 + e0] = v4;
    }
    {
        const float* kvp = g_kv + (size_t)blk * (Ee * Ee);
        #pragma unroll
        for (int t = 0; t < 2; t++) {
            int id = tid + t * 512;
            int e = id >> 4, f0 = (id & 15) * 4;
            *(float4*)&s[CA_SSP + e * 68 + f0] = *(const float4*)(kvp + e * Ee + f0);
        }
        if (tid < Ee) s[CA_SZP + tid] = g_zc[(size_t)blk * Ee + tid];
    }
    __syncthreads();

    // Phase 1: masked A = Q K^T. 8 rows x 4 cols per thread.
    {
        const int ti = tid >> 5, tj = tid & 31;
        const int i0 = ti * 8, j0 = tj * 4;
        float acc[8][4] = {};
        for (int e = 0; e < Ee; e++) {
            float q8[8], k4[4];
            *(float4*)&q8[0] = *(float4*)&s[CA_SQT + e * 132 + i0];
            *(float4*)&q8[4] = *(float4*)&s[CA_SQT + e * 132 + i0 + 4];
            *(float4*)&k4[0] = *(float4*)&s[CA_SKT + e * 132 + j0];
            #pragma unroll
            for (int r = 0; r < 8; r++)
                #pragma unroll
                for (int t = 0; t < 4; t++)
                    acc[r][t] = fmaf(q8[r], k4[t], acc[r][t]);
        }
        #pragma unroll
        for (int r = 0; r < 8; r++)
            #pragma unroll
            for (int t = 0; t < 4; t++) {
                const int i = i0 + r, j = j0 + t;
                s[CA_SA + i * 132 + j] = (j <= i) ? acc[r][t] : 0.f;
            }
    }
    __syncthreads();

    // Phase 2: num = A V + Q S_prev ; den = rowsum(A) + q.z_prev
    {
        const int ti = tid >> 4, tf = tid & 15;
        const int i0 = ti * 4, f0 = tf * 4;
        float acc[4][4] = {};
        float den[4] = {0.f, 0.f, 0.f, 0.f};

        for (int j = 0; j < CL; j++) {
            float a4[4];
            #pragma unroll
            for (int r = 0; r < 4; r++) a4[r] = s[CA_SA + (i0 + r) * 132 + j];
            float v4[4];
            *(float4*)&v4[0] = *(float4*)&s[CA_SV + j * 68 + f0];
            #pragma unroll
            for (int r = 0; r < 4; r++) {
                den[r] += a4[r];
                #pragma unroll
                for (int t = 0; t < 4; t++)
                    acc[r][t] = fmaf(a4[r], v4[t], acc[r][t]);
            }
        }
        for (int e = 0; e < Ee; e++) {
            float q4[4];
            #pragma unroll
            for (int r = 0; r < 4; r++) q4[r] = s[CA_SQT + e * 132 + i0 + r];
            float s4[4];
            *(float4*)&s4[0] = *(float4*)&s[CA_SSP + e * 68 + f0];
            const float zz = s[CA_SZP + e];
            #pragma unroll
            for (int r = 0; r < 4; r++) {
                den[r] = fmaf(q4[r], zz, den[r]);
                #pragma unroll
                for (int t = 0; t < 4; t++)
                    acc[r][t] = fmaf(q4[r], s4[t], acc[r][t]);
            }
        }
        #pragma unroll
        for (int r = 0; r < 4; r++) {
            const float inv = 1.f / (den[r] + 1e-4f);
            const size_t obase = (row0 + i0 + r) * Kdim + h * Ee + f0;
            __half hv[4];
            #pragma unroll
            for (int t = 0; t < 4; t++)
                hv[t] = __float2half_rn(acc[r][t] * inv);
            *(uint2*)(g_ah + obase) = *(uint2*)hv;
        }
    }
}

// ---------------------------------------------------------------------------
// In-place LayerNorm over rows of d_out (4096 rows x 1024).
// ---------------------------------------------------------------------------
__global__ __launch_bounds__(256)
void layernorm_inplace(float* __restrict__ out,
                       const float* __restrict__ gamma,
                       const float* __restrict__ beta)
{
    const int row = blockIdx.x;
    float* p = out + (size_t)row * Dd;
    const int tid = threadIdx.x;

    float4 v = ((const float4*)p)[tid];
    float s = v.x + v.y + v.z + v.w;
    float q = v.x * v.x + v.y * v.y + v.z * v.z + v.w * v.w;

    #pragma unroll
    for (int o = 16; o > 0; o >>= 1) {
        s += __shfl_xor_sync(0xffffffffu, s, o);
        q += __shfl_xor_sync(0xffffffffu, q, o);
    }
    __shared__ float ss[8], sqr[8];
    const int w = tid >> 5, lane = tid & 31;
    if (lane == 0) { ss[w] = s; sqr[w] = q; }
    __syncthreads();
    if (w == 0) {
        s = (lane < 8) ? ss[lane] : 0.f;
        q = (lane < 8) ? sqr[lane] : 0.f;
        #pragma unroll
        for (int o = 4; o > 0; o >>= 1) {
            s += __shfl_xor_sync(0xffffffffu, s, o);
            q += __shfl_xor_sync(0xffffffffu, q, o);
        }
        if (lane == 0) { ss[0] = s; sqr[0] = q; }
    }
    __syncthreads();

    const float mu  = ss[0] * (1.f / 1024.f);
    const float var = sqr[0] * (1.f / 1024.f) - mu * mu;
    const float inv = rsqrtf(var + 1e-5f);

    float4 gv = ((const float4*)gamma)[tid];
    float4 bv = ((const float4*)beta)[tid];
    float4 o4;
    o4.x = (v.x - mu) * inv * gv.x + bv.x;
    o4.y = (v.y - mu) * inv * gv.y + bv.y;
    o4.z = (v.z - mu) * inv * gv.z + bv.z;
    o4.w = (v.w - mu) * inv * gv.w + bv.w;
    ((float4*)p)[tid] = o4;
}

// ---------------------------------------------------------------------------
extern "C" void kernel_launch(void* const* d_in, const int* in_sizes, int n_in,
                              void* d_out, int out_size)
{
    const float* x     = (const float*)d_in[0];
    const float* Wqkv  = (const float*)d_in[1];
    const float* bqkv  = (const float*)d_in[2];
    const float* Wout  = (const float*)d_in[3];
    const float* bout  = (const float*)d_in[4];
    const float* gamma = (const float*)d_in[5];
    const float* beta  = (const float*)d_in[6];
    float* out = (float*)d_out;

    cudaFuncSetAttribute(mma_gemm<true>,  cudaFuncAttributeMaxDynamicSharedMemorySize, GSM);
    cudaFuncSetAttribute(mma_gemm<false>, cudaFuncAttributeMaxDynamicSharedMemorySize, GSM);
    cudaFuncSetAttribute(chunk_kv,   cudaFuncAttributeMaxDynamicSharedMemorySize, CK_TOT);
    cudaFuncSetAttribute(chunk_attn, cudaFuncAttributeMaxDynamicSharedMemorySize, CA_TOT);

    // 0) fp16 conversions of x and both weight matrices (single launch)
    conv_f16_all<<<(NX + NWQ + NWO + 255) / 256, 256>>>(x, Wqkv, Wout);

    // 1) QKV projection (single-term fp16 mma.sync, BK=64) + bias + feature maps
    mma_gemm<true><<<dim3(TD / 128, Mrows / 128), 256, GSM>>>(bqkv, nullptr);

    // 2) Chunked causal linear attention -> g_ah (fp16, fused)
    chunk_kv<<<Bb * Hh * NC, 256, CK_TOT>>>();
    prefix_kv<<<Bb * Hh, 256>>>();
    chunk_attn<<<Bb * Hh * NC, 512, CA_TOT>>>();

    // 3) Output projection (single-term fp16 mma.sync, BK=64) + bias -> d_out
    mma_gemm<false><<<dim3(Dd / 128, Mrows / 128), 256, GSM>>>(bout, out);

    // 4) LayerNorm in place on d_out
    layernorm_inplace<<<Mrows, 256>>>(out, gamma, beta);
}